// round 11
// baseline (speedup 1.0000x reference)
#include <cuda_runtime.h>
#include <cstdint>
#include <cstddef>

#define T_STEPS 2048
#define BATCH   32
#define DIM     512
#define HID     512
#define GATES   2048   // 4*HID

typedef unsigned long long ull;

// 512 MB scratch for gx = x @ w_ih^T + b_ih + b_hh
__device__ float g_gx[134217728];  // T_STEPS*BATCH*GATES

// double-buffered transposed hidden state h_T[buf][u][b]
__device__ __align__(16) float g_ht[2][HID * BATCH];

// per-block progress table: g_step[bid] = (last completed step) + 1
__device__ __align__(16) unsigned int g_step[128];

// ---------------- packed f32x2 helpers (Blackwell FFMA2 path) ----------------
__device__ __forceinline__ void ffma2(ull& d, ull a, ull b) {
    asm("fma.rn.f32x2 %0, %1, %2, %0;" : "+l"(d) : "l"(a), "l"(b));
}
__device__ __forceinline__ ull addf2(ull a, ull b) {
    ull r; asm("add.rn.f32x2 %0, %1, %2;" : "=l"(r) : "l"(a), "l"(b)); return r;
}
__device__ __forceinline__ ull pk2(float x, float y) {
    ull r; asm("mov.b64 %0, {%1, %2};" : "=l"(r) : "f"(x), "f"(y)); return r;
}
__device__ __forceinline__ float2 upk(ull v) {
    float2 r; asm("mov.b64 {%0, %1}, %2;" : "=f"(r.x), "=f"(r.y) : "l"(v)); return r;
}
__device__ __forceinline__ uint4 ld_acq_v4(const unsigned* p) {
    uint4 v;
    asm volatile("ld.acquire.gpu.global.v4.u32 {%0,%1,%2,%3}, [%4];"
                 : "=r"(v.x), "=r"(v.y), "=r"(v.z), "=r"(v.w) : "l"(p) : "memory");
    return v;
}

// ---------------------------------------------------------------------------
// Kernel 1: gx[r][n] = sum_k X[r][k]*W[n][k] + bih[n] + bhh[n]
//   128x128 tile, 8x8 microtile via FFMA2, K-slab 8, double-buffered, occ 2.
// ---------------------------------------------------------------------------
__global__ void __launch_bounds__(256, 2) gemm_gx(
    const float* __restrict__ X,
    const float* __restrict__ W,
    const float* __restrict__ bih,
    const float* __restrict__ bhh)
{
    __shared__ float As[2][8][128];
    __shared__ float Bs[2][8][128];

    const int bm  = blockIdx.y * 128;
    const int bn  = blockIdx.x * 128;
    const int tid = threadIdx.x;
    const int tx  = tid & 15;
    const int ty  = tid >> 4;

    ull acc2[4][8];
#pragma unroll
    for (int i = 0; i < 4; i++)
#pragma unroll
        for (int j = 0; j < 8; j++) acc2[i][j] = 0ull;

    const int lr = tid >> 1;
    const int lk = (tid & 1) * 4;
    const float* Ap = X + (size_t)(bm + lr) * DIM + lk;
    const float* Bp = W + (size_t)(bn + lr) * DIM + lk;

    {
        float4 av = *(const float4*)Ap;
        float4 bv = *(const float4*)Bp;
        As[0][lk + 0][lr] = av.x; As[0][lk + 1][lr] = av.y;
        As[0][lk + 2][lr] = av.z; As[0][lk + 3][lr] = av.w;
        Bs[0][lk + 0][lr] = bv.x; Bs[0][lk + 1][lr] = bv.y;
        Bs[0][lk + 2][lr] = bv.z; Bs[0][lk + 3][lr] = bv.w;
    }
    __syncthreads();

    const int NSLAB = DIM / 8;
    for (int s = 0; s < NSLAB; s++) {
        const int buf = s & 1;
        float4 avn, bvn;
        if (s + 1 < NSLAB) {
            avn = *(const float4*)(Ap + (s + 1) * 8);
            bvn = *(const float4*)(Bp + (s + 1) * 8);
        }
#pragma unroll
        for (int kk = 0; kk < 8; kk++) {
            const ulonglong2* a01 = (const ulonglong2*)&As[buf][kk][ty * 8];
            ulonglong2 al = a01[0];
            ulonglong2 ah = a01[1];
            ull a2[4] = { al.x, al.y, ah.x, ah.y };
            float4 b0 = *(const float4*)&Bs[buf][kk][tx * 8];
            float4 b1 = *(const float4*)&Bs[buf][kk][tx * 8 + 4];
            ull bd[8] = { pk2(b0.x, b0.x), pk2(b0.y, b0.y),
                          pk2(b0.z, b0.z), pk2(b0.w, b0.w),
                          pk2(b1.x, b1.x), pk2(b1.y, b1.y),
                          pk2(b1.z, b1.z), pk2(b1.w, b1.w) };
#pragma unroll
            for (int i2 = 0; i2 < 4; i2++)
#pragma unroll
                for (int j = 0; j < 8; j++)
                    ffma2(acc2[i2][j], a2[i2], bd[j]);
        }
        if (s + 1 < NSLAB) {
            const int nb = buf ^ 1;
            As[nb][lk + 0][lr] = avn.x; As[nb][lk + 1][lr] = avn.y;
            As[nb][lk + 2][lr] = avn.z; As[nb][lk + 3][lr] = avn.w;
            Bs[nb][lk + 0][lr] = bvn.x; Bs[nb][lk + 1][lr] = bvn.y;
            Bs[nb][lk + 2][lr] = bvn.z; Bs[nb][lk + 3][lr] = bvn.w;
            __syncthreads();
        }
    }

    const int row0 = bm + ty * 8;
    const int col0 = bn + tx * 8;
    float bias[8];
#pragma unroll
    for (int j = 0; j < 8; j++) bias[j] = bih[col0 + j] + bhh[col0 + j];

#pragma unroll
    for (int i = 0; i < 8; i++) {
        const int i2 = i >> 1;
        const int s  = i & 1;
        float v[8];
#pragma unroll
        for (int j = 0; j < 8; j++) {
            float2 p = upk(acc2[i2][j]);
            v[j] = (s ? p.y : p.x) + bias[j];
        }
        float* dst = &g_gx[(size_t)(row0 + i) * GATES + col0];
        float4 v0 = { v[0], v[1], v[2], v[3] };
        float4 v1 = { v[4], v[5], v[6], v[7] };
        *(float4*)dst       = v0;
        *(float4*)(dst + 4) = v1;
    }
}

// ---------------------------------------------------------------------------
// init: reset progress table + transpose h0 into g_ht[1][u][b] (step 0 reads buf 1)
// ---------------------------------------------------------------------------
__global__ void init_rec(const float* __restrict__ h0)
{
    int i = blockIdx.x * 256 + threadIdx.x;   // 0..16383
    if (i < 128) g_step[i] = 0u;
    int b = i >> 9;
    int u = i & 511;
    g_ht[1][u * BATCH + b] = h0[i];
}

// ---------------------------------------------------------------------------
// Kernel 2: persistent recurrence. 128 blocks x 256 threads (R5 GEMM core).
//   Sync: per-block st.release into g_step[bid]; consumers poll the whole
//   table with one warp-wide ld.acquire.v4 + __all_sync. No trailing
//   __syncthreads — epi warps close with bar.sync(1,128) + release; GEMM-only
//   warps fall straight through to the next poll.
// ---------------------------------------------------------------------------
#define RBLK 128
#define RTHR 256
// smem floats: WT[512*16]=8192 | RED[8*576]=4608 | CS[128]
#define SMEM_FLOATS (8192 + 4608 + 128)

__global__ void __launch_bounds__(RTHR, 1) lstm_rec(
    const float* __restrict__ c0,
    const float* __restrict__ whh,
    float* __restrict__ out, float* __restrict__ hn, float* __restrict__ cn)
{
    extern __shared__ float sm[];
    float* WT  = sm;             // [k:512][c:16]
    float* RED = sm + 8192;      // [ks:8][b*18 + c]
    float* CS  = RED + 4608;     // [bb*4+uu]

    const int tid = threadIdx.x;
    const int u0  = blockIdx.x * 4;

    // load w_hh slice: local col c = uu*4+gate <-> global row gate*512 + u0+uu
    for (int idx = tid; idx < 8192; idx += RTHR) {
        int c    = idx & 15;
        int k    = idx >> 4;
        int uu   = c >> 2;
        int gate = c & 3;
        int grow = gate * HID + u0 + uu;
        WT[idx] = whh[(size_t)grow * HID + k];
    }
    if (tid < 128) {
        int bb = tid >> 2, uu = tid & 3;
        CS[bb * 4 + uu] = c0[bb * HID + u0 + uu];
    }
    __syncthreads();

    const int ks  = tid >> 5;          // 0..7 K-slice (64 k each)
    const int ln  = tid & 31;
    const int bq  = ln & 7;            // batches 4bq..4bq+3
    const int cq  = ln >> 3;           // cols 4cq..4cq+3
    const int ebb = tid & 31;          // epilogue batch
    const int euu = tid >> 5;          // epilogue unit (tid<128)

    // gx prefetch for t=0
    float gxv[4];
    if (tid < 128) {
        const size_t base = (size_t)ebb * GATES;
#pragma unroll
        for (int g = 0; g < 4; g++)
            gxv[g] = g_gx[base + g * HID + (u0 + euu)];
    }

    for (int t = 0; t < T_STEPS; t++) {
        const int rb = (t & 1) ^ 1;    // read buffer (h_{t-1})
        const int wb = t & 1;          // write buffer (h_t)

        // poll: every block's g_step >= t  (value = completed step + 1)
        if (t > 0) {
            const unsigned tgt = (unsigned)t;
            bool ok;
            do {
                uint4 v = ld_acq_v4(&g_step[ln * 4]);
                ok = (v.x >= tgt) & (v.y >= tgt) & (v.z >= tgt) & (v.w >= tgt);
            } while (!__all_sync(0xffffffffu, ok));
        }

        // 4x4 microtile GEMM; h rows direct from L2 (fresh via ldcg)
        ull acc2[4][2];
#pragma unroll
        for (int i = 0; i < 4; i++) { acc2[i][0] = 0ull; acc2[i][1] = 0ull; }

        const float4* hp = (const float4*)(g_ht[rb] + (ks * 64) * BATCH + bq * 4);
        const float*  wp = WT + (ks * 64) * 16 + cq * 4;
#pragma unroll 16
        for (int k = 0; k < 64; k++) {
            float4 hv = __ldcg(hp); hp += 8;           // +32 floats (one row)
            ulonglong2 wq = *(const ulonglong2*)wp; wp += 16;
            ull h0d = pk2(hv.x, hv.x);
            ull h1d = pk2(hv.y, hv.y);
            ull h2d = pk2(hv.z, hv.z);
            ull h3d = pk2(hv.w, hv.w);
            ffma2(acc2[0][0], h0d, wq.x); ffma2(acc2[0][1], h0d, wq.y);
            ffma2(acc2[1][0], h1d, wq.x); ffma2(acc2[1][1], h1d, wq.y);
            ffma2(acc2[2][0], h2d, wq.x); ffma2(acc2[2][1], h2d, wq.y);
            ffma2(acc2[3][0], h3d, wq.x); ffma2(acc2[3][1], h3d, wq.y);
        }
        // write partials: RED[ks][b:32][c:16 pad 18]
        {
            float* rbuf = RED + ks * 576;
#pragma unroll
            for (int bb = 0; bb < 4; bb++) {
                ull* rp = (ull*)(rbuf + (4 * bq + bb) * 18 + 4 * cq);
                rp[0] = acc2[bb][0];
                rp[1] = acc2[bb][1];
            }
        }
        __syncthreads();   // RED ready for epilogue (warps 4..7 fall through after)

        if (tid < 128) {
            const ull* q = (const ull*)(RED + ebb * 18 + euu * 4);
            ull s01 = 0ull, s23 = 0ull;
#pragma unroll
            for (int kq = 0; kq < 8; kq++) {
                s01 = addf2(s01, q[0]);
                s23 = addf2(s23, q[1]);
                q += 288;   // 576 floats
            }
            float2 p01 = upk(s01);
            float2 p23 = upk(s23);
            float iv = p01.x + gxv[0];
            float fv = p01.y + gxv[1];
            float gv = p23.x + gxv[2];
            float ov = p23.y + gxv[3];
            float it = 1.f / (1.f + __expf(-iv));
            float ft = 1.f / (1.f + __expf(-fv));
            float gt = tanhf(gv);
            float ot = 1.f / (1.f + __expf(-ov));
            float cc  = CS[ebb * 4 + euu];
            float cnv = ft * cc + it * gt;
            CS[ebb * 4 + euu] = cnv;
            float hv = ot * tanhf(cnv);

            // publish h_t (transposed), then release this block
            g_ht[wb][(u0 + euu) * BATCH + ebb] = hv;
            asm volatile("bar.sync 1, 128;" ::: "memory");
            if (tid == 0) {
                asm volatile("st.release.gpu.global.u32 [%0], %1;"
                             :: "l"(&g_step[blockIdx.x]), "r"((unsigned)(t + 1))
                             : "memory");
            }

            // off-critical-path work
            out[(size_t)t * BATCH * HID + ebb * HID + (u0 + euu)] = hv;
            if (t + 1 < T_STEPS) {
                const size_t base = ((size_t)(t + 1) * BATCH + ebb) * GATES;
#pragma unroll
                for (int g = 0; g < 4; g++)
                    gxv[g] = g_gx[base + g * HID + (u0 + euu)];
            } else {
                hn[ebb * HID + (u0 + euu)] = hv;
                cn[ebb * HID + (u0 + euu)] = cnv;
            }
        }
        // warps 4..7 loop straight to the next poll (RED WAR is protected by
        // the global wait: release(t) happens only after epi read RED(t)).
    }
}

// ---------------------------------------------------------------------------
extern "C" void kernel_launch(void* const* d_in, const int* in_sizes, int n_in,
                              void* d_out, int out_size)
{
    const float* x   = (const float*)d_in[0];
    const float* h0  = (const float*)d_in[1];
    const float* c0  = (const float*)d_in[2];
    const float* wih = (const float*)d_in[3];
    const float* bih = (const float*)d_in[4];
    const float* whh = (const float*)d_in[5];
    const float* bhh = (const float*)d_in[6];

    float* out = (float*)d_out;
    float* hn  = out + (size_t)T_STEPS * BATCH * HID;
    float* cn  = hn + BATCH * HID;

    init_rec<<<64, 256>>>(h0);
    gemm_gx<<<dim3(GATES / 128, (T_STEPS * BATCH) / 128), 256>>>(x, wih, bih, bhh);

    const size_t shmem = SMEM_FLOATS * sizeof(float);
    cudaFuncSetAttribute(lstm_rec, cudaFuncAttributeMaxDynamicSharedMemorySize, (int)shmem);
    lstm_rec<<<RBLK, RTHR, shmem>>>(c0, whh, out, hn, cn);
}

// round 12
// speedup vs baseline: 2.4634x; 2.4634x over previous
#include <cuda_runtime.h>
#include <cuda_bf16.h>
#include <cstdint>
#include <cstddef>

#define T_STEPS 2048
#define BATCH   32
#define DIM     512
#define HID     512
#define GATES   2048   // 4*HID

typedef unsigned long long ull;
typedef unsigned int u32;

// 512 MB scratch for gx = x @ w_ih^T + b_ih + b_hh
__device__ float g_gx[134217728];  // T_STEPS*BATCH*GATES

// bf16-split packed inputs: u32 = (hi bf16) | (lo bf16 << 16)
__device__ __align__(16) u32 g_xs[33554432];   // x   [65536, 512]
__device__ __align__(16) u32 g_ws[1048576];    // wih [2048, 512]

// double-buffered transposed hidden state h_T[buf][u][b]
__device__ __align__(16) float g_ht[2][HID * BATCH];

// per-chunk monotonic flags: chunk g = h rows [64g, 64g+64), produced by blocks 16g..16g+15
__device__ unsigned int g_cnt[8];

// ---------------- packed f32x2 helpers (Blackwell FFMA2 path) ----------------
__device__ __forceinline__ void ffma2(ull& d, ull a, ull b) {
    asm("fma.rn.f32x2 %0, %1, %2, %0;" : "+l"(d) : "l"(a), "l"(b));
}
__device__ __forceinline__ ull addf2(ull a, ull b) {
    ull r; asm("add.rn.f32x2 %0, %1, %2;" : "=l"(r) : "l"(a), "l"(b)); return r;
}
__device__ __forceinline__ ull pk2(float x, float y) {
    ull r; asm("mov.b64 %0, {%1, %2};" : "=l"(r) : "f"(x), "f"(y)); return r;
}
__device__ __forceinline__ float2 upk(ull v) {
    float2 r; asm("mov.b64 {%0, %1}, %2;" : "=f"(r.x), "=f"(r.y) : "l"(v)); return r;
}

// ---------------------------------------------------------------------------
// convert_split: pack x and w_ih into (hi|lo) bf16-split u32 arrays
// ---------------------------------------------------------------------------
__device__ __forceinline__ u32 pack_split(float x) {
    __nv_bfloat16 h = __float2bfloat16(x);
    float r = x - __bfloat162float(h);
    __nv_bfloat16 l = __float2bfloat16(r);
    return (u32)__bfloat16_as_ushort(h) | ((u32)__bfloat16_as_ushort(l) << 16);
}

__global__ void convert_split(const float* __restrict__ X, const float* __restrict__ W)
{
    const long long n4x = 33554432LL / 4;   // 8388608
    const long long n4w = 1048576LL / 4;    // 262144
    long long i = (long long)blockIdx.x * blockDim.x + threadIdx.x;
    const float4* src;
    uint4* dst;
    long long j;
    if (i < n4x)            { src = (const float4*)X; dst = (uint4*)g_xs; j = i; }
    else if (i < n4x + n4w) { src = (const float4*)W; dst = (uint4*)g_ws; j = i - n4x; }
    else return;
    float4 v = src[j];
    uint4 o;
    o.x = pack_split(v.x);
    o.y = pack_split(v.y);
    o.z = pack_split(v.z);
    o.w = pack_split(v.w);
    dst[j] = o;
}

// ---------------------------------------------------------------------------
// gemm_bf16x3: gx = x @ wih^T + bih + bhh via m16n8k16 bf16 MMA, 3-term split.
//   Block tile 128x128, 8 warps (m64 x n32 each), K-slab 16, double-buffered.
// ---------------------------------------------------------------------------
#define GP 9   // smem row pitch in u32 (= 18 bf16)

#define MMA_BF16(C, A0, A1, A2, A3, B0, B1)                                    \
    asm volatile(                                                              \
        "mma.sync.aligned.m16n8k16.row.col.f32.bf16.bf16.f32 "                 \
        "{%0,%1,%2,%3},{%4,%5,%6,%7},{%8,%9},{%0,%1,%2,%3};"                   \
        : "+f"((C)[0]), "+f"((C)[1]), "+f"((C)[2]), "+f"((C)[3])               \
        : "r"(A0), "r"(A1), "r"(A2), "r"(A3), "r"(B0), "r"(B1))

__global__ void __launch_bounds__(256, 1) gemm_bf16x3(
    const float* __restrict__ bih,
    const float* __restrict__ bhh)
{
    // smem: [buf:2][Ahi|Alo|Bhi|Blo][128*GP]
    __shared__ u32 smem[2 * 4 * 128 * GP];

    const int tid = threadIdx.x;
    const int bm  = blockIdx.y * 128;
    const int bn  = blockIdx.x * 128;
    const int wid = tid >> 5;
    const int ln  = tid & 31;
    const int mw  = (wid >> 2) * 64;    // warp m-offset within block tile
    const int nw  = (wid & 3) * 32;     // warp n-offset
    const int lc  = ln & 3;             // k-pair / col-pair selector
    const int lr4 = ln >> 2;            // row-within-8 selector

    // loader mapping: thread -> (row, half) ; 8 u32 per thread per slab
    const int lrow  = tid >> 1;
    const int lhalf = tid & 1;
    const u32* Ag = g_xs + (size_t)(bm + lrow) * 512 + lhalf * 8;
    const u32* Bg = g_ws + (size_t)(bn + lrow) * 512 + lhalf * 8;

    float acc[4][4][4];
#pragma unroll
    for (int mt = 0; mt < 4; mt++)
#pragma unroll
        for (int nt = 0; nt < 4; nt++)
#pragma unroll
            for (int q = 0; q < 4; q++) acc[mt][nt][q] = 0.f;

    // per-lane bias pairs for the 4 n-tiles
    float2 bias2[4];
#pragma unroll
    for (int nt = 0; nt < 4; nt++) {
        int c0 = bn + nw + nt * 8 + lc * 2;
        bias2[nt].x = bih[c0]     + bhh[c0];
        bias2[nt].y = bih[c0 + 1] + bhh[c0 + 1];
    }

    const int sts_base = lrow * GP + lhalf * 4;

    // preload + store slab 0
    uint4 pa0 = *(const uint4*)(Ag);
    uint4 pa1 = *(const uint4*)(Ag + 4);
    uint4 pb0 = *(const uint4*)(Bg);
    uint4 pb1 = *(const uint4*)(Bg + 4);
    {
        u32* Ah = smem;               u32* Al = smem + 1152;
        u32* Bh = smem + 2304;        u32* Bl = smem + 3456;
        Ah[sts_base + 0] = __byte_perm(pa0.x, pa0.y, 0x5410);
        Ah[sts_base + 1] = __byte_perm(pa0.z, pa0.w, 0x5410);
        Ah[sts_base + 2] = __byte_perm(pa1.x, pa1.y, 0x5410);
        Ah[sts_base + 3] = __byte_perm(pa1.z, pa1.w, 0x5410);
        Al[sts_base + 0] = __byte_perm(pa0.x, pa0.y, 0x7632);
        Al[sts_base + 1] = __byte_perm(pa0.z, pa0.w, 0x7632);
        Al[sts_base + 2] = __byte_perm(pa1.x, pa1.y, 0x7632);
        Al[sts_base + 3] = __byte_perm(pa1.z, pa1.w, 0x7632);
        Bh[sts_base + 0] = __byte_perm(pb0.x, pb0.y, 0x5410);
        Bh[sts_base + 1] = __byte_perm(pb0.z, pb0.w, 0x5410);
        Bh[sts_base + 2] = __byte_perm(pb1.x, pb1.y, 0x5410);
        Bh[sts_base + 3] = __byte_perm(pb1.z, pb1.w, 0x5410);
        Bl[sts_base + 0] = __byte_perm(pb0.x, pb0.y, 0x7632);
        Bl[sts_base + 1] = __byte_perm(pb0.z, pb0.w, 0x7632);
        Bl[sts_base + 2] = __byte_perm(pb1.x, pb1.y, 0x7632);
        Bl[sts_base + 3] = __byte_perm(pb1.z, pb1.w, 0x7632);
    }
    __syncthreads();

    for (int s = 0; s < 32; s++) {
        if (s + 1 < 32) {
            pa0 = *(const uint4*)(Ag + (s + 1) * 16);
            pa1 = *(const uint4*)(Ag + (s + 1) * 16 + 4);
            pb0 = *(const uint4*)(Bg + (s + 1) * 16);
            pb1 = *(const uint4*)(Bg + (s + 1) * 16 + 4);
        }

        const u32* base = smem + (s & 1) * 4608;
        const u32* Ahi = base;
        const u32* Alo = base + 1152;
        const u32* Bhi = base + 2304;
        const u32* Blo = base + 3456;

        // B fragments for the 4 n-tiles (hi and lo)
        u32 bh[4][2], bl[4][2];
#pragma unroll
        for (int nt = 0; nt < 4; nt++) {
            int r = (nw + nt * 8 + lr4) * GP + lc;
            bh[nt][0] = Bhi[r];     bh[nt][1] = Bhi[r + 4];
            bl[nt][0] = Blo[r];     bl[nt][1] = Blo[r + 4];
        }

#pragma unroll
        for (int mt = 0; mt < 4; mt++) {
            int r0 = (mw + mt * 16 + lr4) * GP + lc;
            int r1 = r0 + 8 * GP;
            u32 ah0 = Ahi[r0], ah1 = Ahi[r1], ah2 = Ahi[r0 + 4], ah3 = Ahi[r1 + 4];
            u32 al0 = Alo[r0], al1 = Alo[r1], al2 = Alo[r0 + 4], al3 = Alo[r1 + 4];
#pragma unroll
            for (int nt = 0; nt < 4; nt++) {
                MMA_BF16(acc[mt][nt], ah0, ah1, ah2, ah3, bh[nt][0], bh[nt][1]);
                MMA_BF16(acc[mt][nt], ah0, ah1, ah2, ah3, bl[nt][0], bl[nt][1]);
                MMA_BF16(acc[mt][nt], al0, al1, al2, al3, bh[nt][0], bh[nt][1]);
            }
        }

        if (s + 1 < 32) {
            u32* nb = smem + ((s + 1) & 1) * 4608;
            u32* Ah = nb;          u32* Al = nb + 1152;
            u32* Bh = nb + 2304;   u32* Bl = nb + 3456;
            Ah[sts_base + 0] = __byte_perm(pa0.x, pa0.y, 0x5410);
            Ah[sts_base + 1] = __byte_perm(pa0.z, pa0.w, 0x5410);
            Ah[sts_base + 2] = __byte_perm(pa1.x, pa1.y, 0x5410);
            Ah[sts_base + 3] = __byte_perm(pa1.z, pa1.w, 0x5410);
            Al[sts_base + 0] = __byte_perm(pa0.x, pa0.y, 0x7632);
            Al[sts_base + 1] = __byte_perm(pa0.z, pa0.w, 0x7632);
            Al[sts_base + 2] = __byte_perm(pa1.x, pa1.y, 0x7632);
            Al[sts_base + 3] = __byte_perm(pa1.z, pa1.w, 0x7632);
            Bh[sts_base + 0] = __byte_perm(pb0.x, pb0.y, 0x5410);
            Bh[sts_base + 1] = __byte_perm(pb0.z, pb0.w, 0x5410);
            Bh[sts_base + 2] = __byte_perm(pb1.x, pb1.y, 0x5410);
            Bh[sts_base + 3] = __byte_perm(pb1.z, pb1.w, 0x5410);
            Bl[sts_base + 0] = __byte_perm(pb0.x, pb0.y, 0x7632);
            Bl[sts_base + 1] = __byte_perm(pb0.z, pb0.w, 0x7632);
            Bl[sts_base + 2] = __byte_perm(pb1.x, pb1.y, 0x7632);
            Bl[sts_base + 3] = __byte_perm(pb1.z, pb1.w, 0x7632);
            __syncthreads();
        }
    }

    // epilogue: C frag (c0,c1)=row lr4, cols 2lc..2lc+1; (c2,c3)=row lr4+8
#pragma unroll
    for (int mt = 0; mt < 4; mt++) {
        int grow = bm + mw + mt * 16 + lr4;
#pragma unroll
        for (int nt = 0; nt < 4; nt++) {
            int gcol = bn + nw + nt * 8 + lc * 2;
            float2 v0 = { acc[mt][nt][0] + bias2[nt].x,
                          acc[mt][nt][1] + bias2[nt].y };
            float2 v1 = { acc[mt][nt][2] + bias2[nt].x,
                          acc[mt][nt][3] + bias2[nt].y };
            *(float2*)&g_gx[(size_t)grow * GATES + gcol]       = v0;
            *(float2*)&g_gx[(size_t)(grow + 8) * GATES + gcol] = v1;
        }
    }
}

// ---------------------------------------------------------------------------
// init: reset chunk flags + transpose h0 into g_ht[1][u][b]  (step 0 reads buf 1)
// ---------------------------------------------------------------------------
__global__ void init_rec(const float* __restrict__ h0)
{
    int i = blockIdx.x * 256 + threadIdx.x;   // 0..16383
    if (i < 8) g_cnt[i] = 0u;
    int b = i >> 9;
    int u = i & 511;
    g_ht[1][u * BATCH + b] = h0[i];
}

// ---------------------------------------------------------------------------
// Kernel 2: persistent recurrence — byte-for-byte the R5 kernel (11244 us).
// ---------------------------------------------------------------------------
#define RBLK 128
#define RTHR 256
// smem floats: WT[512*16]=8192 | RED[8*576]=4608 | CS[128]
#define SMEM_FLOATS (8192 + 4608 + 128)

__global__ void __launch_bounds__(RTHR, 1) lstm_rec(
    const float* __restrict__ c0,
    const float* __restrict__ whh,
    float* __restrict__ out, float* __restrict__ hn, float* __restrict__ cn)
{
    extern __shared__ float sm[];
    float* WT  = sm;             // [k:512][c:16]
    float* RED = sm + 8192;      // [ks:8][b*18 + c]
    float* CS  = RED + 4608;     // [bb*4+uu]

    const int tid = threadIdx.x;
    const int u0  = blockIdx.x * 4;
    const int my_chunk = blockIdx.x >> 4;     // chunk this block produces

    // load w_hh slice: local col c = uu*4+gate <-> global row gate*512 + u0+uu
    for (int idx = tid; idx < 8192; idx += RTHR) {
        int c    = idx & 15;
        int k    = idx >> 4;
        int uu   = c >> 2;
        int gate = c & 3;
        int grow = gate * HID + u0 + uu;
        WT[idx] = whh[(size_t)grow * HID + k];
    }
    if (tid < 128) {
        int bb = tid >> 2, uu = tid & 3;
        CS[bb * 4 + uu] = c0[bb * HID + u0 + uu];
    }
    __syncthreads();

    const int ks  = tid >> 5;          // 0..7  (also = chunk this warp consumes)
    const int ln  = tid & 31;
    const int bq  = ln & 7;            // batches 4bq..4bq+3
    const int cq  = ln >> 3;           // cols 4cq..4cq+3
    const int ebb = tid & 31;          // epilogue batch
    const int euu = tid >> 5;          // epilogue unit (tid<128)

    // gx prefetch for t=0
    float gxv[4];
    if (tid < 128) {
        const size_t base = (size_t)ebb * GATES;
#pragma unroll
        for (int g = 0; g < 4; g++)
            gxv[g] = g_gx[base + g * HID + (u0 + euu)];
    }

    for (int t = 0; t < T_STEPS; t++) {
        const int rb = (t & 1) ^ 1;    // read buffer (h_{t-1})
        const int wb = t & 1;          // write buffer (h_t)

        // per-warp chunk wait: h_{t-1} rows 64ks.. ready when g_cnt[ks] >= 16*t
        if (t > 0) {
            if (ln == 0) {
                const unsigned tgt = 16u * (unsigned)t;
                unsigned v;
                do {
                    asm volatile("ld.acquire.gpu.global.u32 %0, [%1];"
                                 : "=r"(v) : "l"(&g_cnt[ks]) : "memory");
                } while (v < tgt);
            }
            __syncwarp();
        }

        // 4x4 microtile GEMM; h rows direct from L2 (fresh via ldcg)
        ull acc2[4][2];
#pragma unroll
        for (int i = 0; i < 4; i++) { acc2[i][0] = 0ull; acc2[i][1] = 0ull; }

        const float4* hp = (const float4*)(g_ht[rb] + (ks * 64) * BATCH + bq * 4);
        const float*  wp = WT + (ks * 64) * 16 + cq * 4;
#pragma unroll 16
        for (int k = 0; k < 64; k++) {
            float4 hv = __ldcg(hp); hp += 8;           // +32 floats (one row)
            ulonglong2 wq = *(const ulonglong2*)wp; wp += 16;
            ull h0d = pk2(hv.x, hv.x);
            ull h1d = pk2(hv.y, hv.y);
            ull h2d = pk2(hv.z, hv.z);
            ull h3d = pk2(hv.w, hv.w);
            ffma2(acc2[0][0], h0d, wq.x); ffma2(acc2[0][1], h0d, wq.y);
            ffma2(acc2[1][0], h1d, wq.x); ffma2(acc2[1][1], h1d, wq.y);
            ffma2(acc2[2][0], h2d, wq.x); ffma2(acc2[2][1], h2d, wq.y);
            ffma2(acc2[3][0], h3d, wq.x); ffma2(acc2[3][1], h3d, wq.y);
        }
        // write partials: RED[ks][b:32][c:16 pad 18]
        {
            float* rbuf = RED + ks * 576;
#pragma unroll
            for (int bb = 0; bb < 4; bb++) {
                ull* rp = (ull*)(rbuf + (4 * bq + bb) * 18 + 4 * cq);
                rp[0] = acc2[bb][0];
                rp[1] = acc2[bb][1];
            }
        }
        __syncthreads();

        if (tid < 128) {
            const ull* q = (const ull*)(RED + ebb * 18 + euu * 4);
            ull s01 = 0ull, s23 = 0ull;
#pragma unroll
            for (int kq = 0; kq < 8; kq++) {
                s01 = addf2(s01, q[0]);
                s23 = addf2(s23, q[1]);
                q += 288;   // 576 floats
            }
            float2 p01 = upk(s01);
            float2 p23 = upk(s23);
            float iv = p01.x + gxv[0];
            float fv = p01.y + gxv[1];
            float gv = p23.x + gxv[2];
            float ov = p23.y + gxv[3];
            float it = 1.f / (1.f + __expf(-iv));
            float ft = 1.f / (1.f + __expf(-fv));
            float gt = tanhf(gv);
            float ot = 1.f / (1.f + __expf(-ov));
            float cc  = CS[ebb * 4 + euu];
            float cnv = ft * cc + it * gt;
            CS[ebb * 4 + euu] = cnv;
            float hv = ot * tanhf(cnv);
            g_ht[wb][(u0 + euu) * BATCH + ebb] = hv;   // publish h_t (transposed)
            out[(size_t)t * BATCH * HID + ebb * HID + (u0 + euu)] = hv;
            if (t == T_STEPS - 1) {
                hn[ebb * HID + (u0 + euu)] = hv;
                cn[ebb * HID + (u0 + euu)] = cnv;
            }
        }

        // prefetch gx for t+1 (independent of the barrier)
        if (tid < 128 && t + 1 < T_STEPS) {
            const size_t base = ((size_t)(t + 1) * BATCH + ebb) * GATES;
#pragma unroll
            for (int g = 0; g < 4; g++)
                gxv[g] = g_gx[base + g * HID + (u0 + euu)];
        }

        // block-wide publish, then release this block's chunk
        if (t < T_STEPS - 1) {
            __syncthreads();
            if (tid == 0) {
                asm volatile("red.release.gpu.global.add.u32 [%0], 1;"
                             :: "l"(&g_cnt[my_chunk]) : "memory");
            }
        }
    }
}

// ---------------------------------------------------------------------------
extern "C" void kernel_launch(void* const* d_in, const int* in_sizes, int n_in,
                              void* d_out, int out_size)
{
    const float* x   = (const float*)d_in[0];
    const float* h0  = (const float*)d_in[1];
    const float* c0  = (const float*)d_in[2];
    const float* wih = (const float*)d_in[3];
    const float* bih = (const float*)d_in[4];
    const float* whh = (const float*)d_in[5];
    const float* bhh = (const float*)d_in[6];

    float* out = (float*)d_out;
    float* hn  = out + (size_t)T_STEPS * BATCH * HID;
    float* cn  = hn + BATCH * HID;

    init_rec<<<64, 256>>>(h0);
    convert_split<<<33792, 256>>>(x, wih);
    gemm_bf16x3<<<dim3(GATES / 128, (T_STEPS * BATCH) / 128), 256>>>(bih, bhh);

    const size_t shmem = SMEM_FLOATS * sizeof(float);
    cudaFuncSetAttribute(lstm_rec, cudaFuncAttributeMaxDynamicSharedMemorySize, (int)shmem);
    lstm_rec<<<RBLK, RTHR, shmem>>>(c0, whh, out, hn, cn);
}

// round 13
// speedup vs baseline: 2.7457x; 1.1146x over previous
#include <cuda_runtime.h>
#include <cuda_bf16.h>
#include <cstdint>
#include <cstddef>

#define T_STEPS 2048
#define BATCH   32
#define DIM     512
#define HID     512
#define GATES   2048   // 4*HID

typedef unsigned long long ull;
typedef unsigned int u32;

// 512 MB scratch for gx = x @ w_ih^T + b_ih + b_hh
__device__ float g_gx[134217728];  // T_STEPS*BATCH*GATES

// bf16-split packed inputs: u32 = (hi bf16) | (lo bf16 << 16)
__device__ __align__(16) u32 g_xs[33554432];   // x   [65536, 512]
__device__ __align__(16) u32 g_ws[1048576];    // wih [2048, 512]

// double-buffered transposed hidden state h_T[buf][u][b]
__device__ __align__(16) float g_ht[2][HID * BATCH];

// per-chunk monotonic flags: chunk g = h rows [64g, 64g+64), produced by blocks 16g..16g+15
__device__ unsigned int g_cnt[8];

// ---------------- packed f32x2 helpers (Blackwell FFMA2 path) ----------------
__device__ __forceinline__ void ffma2(ull& d, ull a, ull b) {
    asm("fma.rn.f32x2 %0, %1, %2, %0;" : "+l"(d) : "l"(a), "l"(b));
}
__device__ __forceinline__ ull addf2(ull a, ull b) {
    ull r; asm("add.rn.f32x2 %0, %1, %2;" : "=l"(r) : "l"(a), "l"(b)); return r;
}
__device__ __forceinline__ ull pk2(float x, float y) {
    ull r; asm("mov.b64 %0, {%1, %2};" : "=l"(r) : "f"(x), "f"(y)); return r;
}
__device__ __forceinline__ float2 upk(ull v) {
    float2 r; asm("mov.b64 {%0, %1}, %2;" : "=f"(r.x), "=f"(r.y) : "l"(v)); return r;
}

// ---------------------------------------------------------------------------
// convert_split: pack x and w_ih into (hi|lo) bf16-split u32 arrays
// ---------------------------------------------------------------------------
__device__ __forceinline__ u32 pack_split(float x) {
    __nv_bfloat16 h = __float2bfloat16(x);
    float r = x - __bfloat162float(h);
    __nv_bfloat16 l = __float2bfloat16(r);
    return (u32)__bfloat16_as_ushort(h) | ((u32)__bfloat16_as_ushort(l) << 16);
}

__global__ void convert_split(const float* __restrict__ X, const float* __restrict__ W)
{
    const long long n4x = 33554432LL / 4;   // 8388608
    const long long n4w = 1048576LL / 4;    // 262144
    long long i = (long long)blockIdx.x * blockDim.x + threadIdx.x;
    const float4* src;
    uint4* dst;
    long long j;
    if (i < n4x)            { src = (const float4*)X; dst = (uint4*)g_xs; j = i; }
    else if (i < n4x + n4w) { src = (const float4*)W; dst = (uint4*)g_ws; j = i - n4x; }
    else return;
    float4 v = src[j];
    uint4 o;
    o.x = pack_split(v.x);
    o.y = pack_split(v.y);
    o.z = pack_split(v.z);
    o.w = pack_split(v.w);
    dst[j] = o;
}

// ---------------------------------------------------------------------------
// gemm_bf16x3: gx = x @ wih^T + bih + bhh via m16n8k16 bf16 MMA, 3-term split.
//   Block tile 128x128, 8 warps (m64 x n32 each), K-slab 16, double-buffered.
// ---------------------------------------------------------------------------
#define GP 9   // smem row pitch in u32 (= 18 bf16)

#define MMA_BF16(C, A0, A1, A2, A3, B0, B1)                                    \
    asm volatile(                                                              \
        "mma.sync.aligned.m16n8k16.row.col.f32.bf16.bf16.f32 "                 \
        "{%0,%1,%2,%3},{%4,%5,%6,%7},{%8,%9},{%0,%1,%2,%3};"                   \
        : "+f"((C)[0]), "+f"((C)[1]), "+f"((C)[2]), "+f"((C)[3])               \
        : "r"(A0), "r"(A1), "r"(A2), "r"(A3), "r"(B0), "r"(B1))

__global__ void __launch_bounds__(256, 2) gemm_bf16x3(
    const float* __restrict__ bih,
    const float* __restrict__ bhh)
{
    // smem: [buf:2][Ahi|Alo|Bhi|Blo][128*GP]
    __shared__ u32 smem[2 * 4 * 128 * GP];

    const int tid = threadIdx.x;
    const int bm  = blockIdx.y * 128;
    const int bn  = blockIdx.x * 128;
    const int wid = tid >> 5;
    const int ln  = tid & 31;
    const int mw  = (wid >> 2) * 64;    // warp m-offset within block tile
    const int nw  = (wid & 3) * 32;     // warp n-offset
    const int lc  = ln & 3;             // k-pair / col-pair selector
    const int lr4 = ln >> 2;            // row-within-8 selector

    // loader mapping: thread -> (row, half) ; 8 u32 per thread per slab
    const int lrow  = tid >> 1;
    const int lhalf = tid & 1;
    const u32* Ag = g_xs + (size_t)(bm + lrow) * 512 + lhalf * 8;
    const u32* Bg = g_ws + (size_t)(bn + lrow) * 512 + lhalf * 8;

    float acc[4][4][4];
#pragma unroll
    for (int mt = 0; mt < 4; mt++)
#pragma unroll
        for (int nt = 0; nt < 4; nt++)
#pragma unroll
            for (int q = 0; q < 4; q++) acc[mt][nt][q] = 0.f;

    // per-lane bias pairs for the 4 n-tiles
    float2 bias2[4];
#pragma unroll
    for (int nt = 0; nt < 4; nt++) {
        int c0 = bn + nw + nt * 8 + lc * 2;
        bias2[nt].x = bih[c0]     + bhh[c0];
        bias2[nt].y = bih[c0 + 1] + bhh[c0 + 1];
    }

    const int sts_base = lrow * GP + lhalf * 4;

    // preload + store slab 0
    uint4 pa0 = *(const uint4*)(Ag);
    uint4 pa1 = *(const uint4*)(Ag + 4);
    uint4 pb0 = *(const uint4*)(Bg);
    uint4 pb1 = *(const uint4*)(Bg + 4);
    {
        u32* Ah = smem;               u32* Al = smem + 1152;
        u32* Bh = smem + 2304;        u32* Bl = smem + 3456;
        Ah[sts_base + 0] = __byte_perm(pa0.x, pa0.y, 0x5410);
        Ah[sts_base + 1] = __byte_perm(pa0.z, pa0.w, 0x5410);
        Ah[sts_base + 2] = __byte_perm(pa1.x, pa1.y, 0x5410);
        Ah[sts_base + 3] = __byte_perm(pa1.z, pa1.w, 0x5410);
        Al[sts_base + 0] = __byte_perm(pa0.x, pa0.y, 0x7632);
        Al[sts_base + 1] = __byte_perm(pa0.z, pa0.w, 0x7632);
        Al[sts_base + 2] = __byte_perm(pa1.x, pa1.y, 0x7632);
        Al[sts_base + 3] = __byte_perm(pa1.z, pa1.w, 0x7632);
        Bh[sts_base + 0] = __byte_perm(pb0.x, pb0.y, 0x5410);
        Bh[sts_base + 1] = __byte_perm(pb0.z, pb0.w, 0x5410);
        Bh[sts_base + 2] = __byte_perm(pb1.x, pb1.y, 0x5410);
        Bh[sts_base + 3] = __byte_perm(pb1.z, pb1.w, 0x5410);
        Bl[sts_base + 0] = __byte_perm(pb0.x, pb0.y, 0x7632);
        Bl[sts_base + 1] = __byte_perm(pb0.z, pb0.w, 0x7632);
        Bl[sts_base + 2] = __byte_perm(pb1.x, pb1.y, 0x7632);
        Bl[sts_base + 3] = __byte_perm(pb1.z, pb1.w, 0x7632);
    }
    __syncthreads();

    for (int s = 0; s < 32; s++) {
        if (s + 1 < 32) {
            pa0 = *(const uint4*)(Ag + (s + 1) * 16);
            pa1 = *(const uint4*)(Ag + (s + 1) * 16 + 4);
            pb0 = *(const uint4*)(Bg + (s + 1) * 16);
            pb1 = *(const uint4*)(Bg + (s + 1) * 16 + 4);
        }

        const u32* base = smem + (s & 1) * 4608;
        const u32* Ahi = base;
        const u32* Alo = base + 1152;
        const u32* Bhi = base + 2304;
        const u32* Blo = base + 3456;

        // B fragments for the 4 n-tiles (hi and lo)
        u32 bh[4][2], bl[4][2];
#pragma unroll
        for (int nt = 0; nt < 4; nt++) {
            int r = (nw + nt * 8 + lr4) * GP + lc;
            bh[nt][0] = Bhi[r];     bh[nt][1] = Bhi[r + 4];
            bl[nt][0] = Blo[r];     bl[nt][1] = Blo[r + 4];
        }

#pragma unroll
        for (int mt = 0; mt < 4; mt++) {
            int r0 = (mw + mt * 16 + lr4) * GP + lc;
            int r1 = r0 + 8 * GP;
            u32 ah0 = Ahi[r0], ah1 = Ahi[r1], ah2 = Ahi[r0 + 4], ah3 = Ahi[r1 + 4];
            u32 al0 = Alo[r0], al1 = Alo[r1], al2 = Alo[r0 + 4], al3 = Alo[r1 + 4];
#pragma unroll
            for (int nt = 0; nt < 4; nt++) {
                MMA_BF16(acc[mt][nt], ah0, ah1, ah2, ah3, bh[nt][0], bh[nt][1]);
                MMA_BF16(acc[mt][nt], ah0, ah1, ah2, ah3, bl[nt][0], bl[nt][1]);
                MMA_BF16(acc[mt][nt], al0, al1, al2, al3, bh[nt][0], bh[nt][1]);
            }
        }

        if (s + 1 < 32) {
            u32* nb = smem + ((s + 1) & 1) * 4608;
            u32* Ah = nb;          u32* Al = nb + 1152;
            u32* Bh = nb + 2304;   u32* Bl = nb + 3456;
            Ah[sts_base + 0] = __byte_perm(pa0.x, pa0.y, 0x5410);
            Ah[sts_base + 1] = __byte_perm(pa0.z, pa0.w, 0x5410);
            Ah[sts_base + 2] = __byte_perm(pa1.x, pa1.y, 0x5410);
            Ah[sts_base + 3] = __byte_perm(pa1.z, pa1.w, 0x5410);
            Al[sts_base + 0] = __byte_perm(pa0.x, pa0.y, 0x7632);
            Al[sts_base + 1] = __byte_perm(pa0.z, pa0.w, 0x7632);
            Al[sts_base + 2] = __byte_perm(pa1.x, pa1.y, 0x7632);
            Al[sts_base + 3] = __byte_perm(pa1.z, pa1.w, 0x7632);
            Bh[sts_base + 0] = __byte_perm(pb0.x, pb0.y, 0x5410);
            Bh[sts_base + 1] = __byte_perm(pb0.z, pb0.w, 0x5410);
            Bh[sts_base + 2] = __byte_perm(pb1.x, pb1.y, 0x5410);
            Bh[sts_base + 3] = __byte_perm(pb1.z, pb1.w, 0x5410);
            Bl[sts_base + 0] = __byte_perm(pb0.x, pb0.y, 0x7632);
            Bl[sts_base + 1] = __byte_perm(pb0.z, pb0.w, 0x7632);
            Bl[sts_base + 2] = __byte_perm(pb1.x, pb1.y, 0x7632);
            Bl[sts_base + 3] = __byte_perm(pb1.z, pb1.w, 0x7632);
            __syncthreads();
        }
    }

    // epilogue: C frag (c0,c1)=row lr4, cols 2lc..2lc+1; (c2,c3)=row lr4+8
#pragma unroll
    for (int mt = 0; mt < 4; mt++) {
        int grow = bm + mw + mt * 16 + lr4;
#pragma unroll
        for (int nt = 0; nt < 4; nt++) {
            int gcol = bn + nw + nt * 8 + lc * 2;
            float2 v0 = { acc[mt][nt][0] + bias2[nt].x,
                          acc[mt][nt][1] + bias2[nt].y };
            float2 v1 = { acc[mt][nt][2] + bias2[nt].x,
                          acc[mt][nt][3] + bias2[nt].y };
            *(float2*)&g_gx[(size_t)grow * GATES + gcol]       = v0;
            *(float2*)&g_gx[(size_t)(grow + 8) * GATES + gcol] = v1;
        }
    }
}

// ---------------------------------------------------------------------------
// init: reset chunk flags + transpose h0 into g_ht[1][u][b]  (step 0 reads buf 1)
// ---------------------------------------------------------------------------
__global__ void init_rec(const float* __restrict__ h0)
{
    int i = blockIdx.x * 256 + threadIdx.x;   // 0..16383
    if (i < 8) g_cnt[i] = 0u;
    int b = i >> 9;
    int u = i & 511;
    g_ht[1][u * BATCH + b] = h0[i];
}

// ---------------------------------------------------------------------------
// Kernel 2: persistent recurrence — R5 core with early release:
//   h-store -> bar.sync(1,128) (epi warps only) -> release -> out/prefetch.
//   Trailing __syncthreads removed; RED WAR protected by the chunk wait.
// ---------------------------------------------------------------------------
#define RBLK 128
#define RTHR 256
// smem floats: WT[512*16]=8192 | RED[8*576]=4608 | CS[128]
#define SMEM_FLOATS (8192 + 4608 + 128)

__global__ void __launch_bounds__(RTHR, 1) lstm_rec(
    const float* __restrict__ c0,
    const float* __restrict__ whh,
    float* __restrict__ out, float* __restrict__ hn, float* __restrict__ cn)
{
    extern __shared__ float sm[];
    float* WT  = sm;             // [k:512][c:16]
    float* RED = sm + 8192;      // [ks:8][b*18 + c]
    float* CS  = RED + 4608;     // [bb*4+uu]

    const int tid = threadIdx.x;
    const int u0  = blockIdx.x * 4;
    const int my_chunk = blockIdx.x >> 4;     // chunk this block produces

    // load w_hh slice: local col c = uu*4+gate <-> global row gate*512 + u0+uu
    for (int idx = tid; idx < 8192; idx += RTHR) {
        int c    = idx & 15;
        int k    = idx >> 4;
        int uu   = c >> 2;
        int gate = c & 3;
        int grow = gate * HID + u0 + uu;
        WT[idx] = whh[(size_t)grow * HID + k];
    }
    if (tid < 128) {
        int bb = tid >> 2, uu = tid & 3;
        CS[bb * 4 + uu] = c0[bb * HID + u0 + uu];
    }
    __syncthreads();

    const int ks  = tid >> 5;          // 0..7  (also = chunk this warp consumes)
    const int ln  = tid & 31;
    const int bq  = ln & 7;            // batches 4bq..4bq+3
    const int cq  = ln >> 3;           // cols 4cq..4cq+3
    const int ebb = tid & 31;          // epilogue batch
    const int euu = tid >> 5;          // epilogue unit (tid<128)

    // gx prefetch for t=0
    float gxv[4];
    if (tid < 128) {
        const size_t base = (size_t)ebb * GATES;
#pragma unroll
        for (int g = 0; g < 4; g++)
            gxv[g] = g_gx[base + g * HID + (u0 + euu)];
    }

    for (int t = 0; t < T_STEPS; t++) {
        const int rb = (t & 1) ^ 1;    // read buffer (h_{t-1})
        const int wb = t & 1;          // write buffer (h_t)

        // per-warp chunk wait: h_{t-1} rows 64ks.. ready when g_cnt[ks] >= 16*t
        if (t > 0) {
            if (ln == 0) {
                const unsigned tgt = 16u * (unsigned)t;
                unsigned v;
                do {
                    asm volatile("ld.acquire.gpu.global.u32 %0, [%1];"
                                 : "=r"(v) : "l"(&g_cnt[ks]) : "memory");
                } while (v < tgt);
            }
            __syncwarp();
        }

        // 4x4 microtile GEMM; h rows direct from L2 (fresh via ldcg)
        ull acc2[4][2];
#pragma unroll
        for (int i = 0; i < 4; i++) { acc2[i][0] = 0ull; acc2[i][1] = 0ull; }

        const float4* hp = (const float4*)(g_ht[rb] + (ks * 64) * BATCH + bq * 4);
        const float*  wp = WT + (ks * 64) * 16 + cq * 4;
#pragma unroll 16
        for (int k = 0; k < 64; k++) {
            float4 hv = __ldcg(hp); hp += 8;           // +32 floats (one row)
            ulonglong2 wq = *(const ulonglong2*)wp; wp += 16;
            ull h0d = pk2(hv.x, hv.x);
            ull h1d = pk2(hv.y, hv.y);
            ull h2d = pk2(hv.z, hv.z);
            ull h3d = pk2(hv.w, hv.w);
            ffma2(acc2[0][0], h0d, wq.x); ffma2(acc2[0][1], h0d, wq.y);
            ffma2(acc2[1][0], h1d, wq.x); ffma2(acc2[1][1], h1d, wq.y);
            ffma2(acc2[2][0], h2d, wq.x); ffma2(acc2[2][1], h2d, wq.y);
            ffma2(acc2[3][0], h3d, wq.x); ffma2(acc2[3][1], h3d, wq.y);
        }
        // write partials: RED[ks][b:32][c:16 pad 18]
        {
            float* rbuf = RED + ks * 576;
#pragma unroll
            for (int bb = 0; bb < 4; bb++) {
                ull* rp = (ull*)(rbuf + (4 * bq + bb) * 18 + 4 * cq);
                rp[0] = acc2[bb][0];
                rp[1] = acc2[bb][1];
            }
        }
        __syncthreads();   // RED ready; warps 4..7 fall through to next poll

        if (tid < 128) {
            const ull* q = (const ull*)(RED + ebb * 18 + euu * 4);
            ull s01 = 0ull, s23 = 0ull;
#pragma unroll
            for (int kq = 0; kq < 8; kq++) {
                s01 = addf2(s01, q[0]);
                s23 = addf2(s23, q[1]);
                q += 288;   // 576 floats
            }
            float2 p01 = upk(s01);
            float2 p23 = upk(s23);
            float iv = p01.x + gxv[0];
            float fv = p01.y + gxv[1];
            float gv = p23.x + gxv[2];
            float ov = p23.y + gxv[3];
            float it = 1.f / (1.f + __expf(-iv));
            float ft = 1.f / (1.f + __expf(-fv));
            float gt = tanhf(gv);
            float ot = 1.f / (1.f + __expf(-ov));
            float cc  = CS[ebb * 4 + euu];
            float cnv = ft * cc + it * gt;
            CS[ebb * 4 + euu] = cnv;
            float hv = ot * tanhf(cnv);

            // publish h_t, then release ASAP (epi-warp barrier only)
            g_ht[wb][(u0 + euu) * BATCH + ebb] = hv;
            asm volatile("bar.sync 1, 128;" ::: "memory");
            if (tid == 0 && t < T_STEPS - 1) {
                asm volatile("red.release.gpu.global.add.u32 [%0], 1;"
                             :: "l"(&g_cnt[my_chunk]) : "memory");
            }

            // off-critical-path work
            out[(size_t)t * BATCH * HID + ebb * HID + (u0 + euu)] = hv;
            if (t + 1 < T_STEPS) {
                const size_t base = ((size_t)(t + 1) * BATCH + ebb) * GATES;
#pragma unroll
                for (int g = 0; g < 4; g++)
                    gxv[g] = g_gx[base + g * HID + (u0 + euu)];
            } else {
                hn[ebb * HID + (u0 + euu)] = hv;
                cn[ebb * HID + (u0 + euu)] = cnv;
            }
        }
        // warps 4..7 loop straight to the next chunk wait (RED WAR is safe:
        // they pass wait(t+1) only after ALL blocks released t, i.e. after our
        // epi warps finished reading RED(t)).
    }
}

// ---------------------------------------------------------------------------
extern "C" void kernel_launch(void* const* d_in, const int* in_sizes, int n_in,
                              void* d_out, int out_size)
{
    const float* x   = (const float*)d_in[0];
    const float* h0  = (const float*)d_in[1];
    const float* c0  = (const float*)d_in[2];
    const float* wih = (const float*)d_in[3];
    const float* bih = (const float*)d_in[4];
    const float* whh = (const float*)d_in[5];
    const float* bhh = (const float*)d_in[6];

    float* out = (float*)d_out;
    float* hn  = out + (size_t)T_STEPS * BATCH * HID;
    float* cn  = hn + BATCH * HID;

    init_rec<<<64, 256>>>(h0);
    convert_split<<<33792, 256>>>(x, wih);
    gemm_bf16x3<<<dim3(GATES / 128, (T_STEPS * BATCH) / 128), 256>>>(bih, bhh);

    const size_t shmem = SMEM_FLOATS * sizeof(float);
    cudaFuncSetAttribute(lstm_rec, cudaFuncAttributeMaxDynamicSharedMemorySize, (int)shmem);
    lstm_rec<<<RBLK, RTHR, shmem>>>(c0, whh, out, hn, cn);
}